// round 1
// baseline (speedup 1.0000x reference)
#include <cuda_runtime.h>

#define NPTS 1024
#define DIM  64
#define AH   256
#define TI   16     // i-rows per CTA in the layer kernel
#define JS   16     // j-range splits (partial softmax)

// ---------------- device scratch (no allocations allowed) ----------------
__device__ float g_feats[2][NPTS*DIM];
__device__ float g_qkv[NPTS*3*DIM];
__device__ float g_a [NPTS*DIM];     // pos @ pw1
__device__ float g_c [NPTS*AH];      // q@aw1 + pb2@aw1 + ab1
__device__ float g_ka[NPTS*AH];      // k@aw1
__device__ float g_vp[NPTS*DIM];     // v + pb2
__device__ float g_W [DIM*AH];       // pw2 @ aw1
__device__ float g_cbias[AH];        // pb2@aw1 + ab1
__device__ float g_f1[NPTS*DIM];
__device__ float g_pm[JS*NPTS*DIM];  // partial softmax max
__device__ float g_ps[JS*NPTS*DIM];  // partial softmax sum
__device__ float g_pa[JS*NPTS*DIM];  // partial weighted acc

// ---------------- small prep kernels ----------------
__global__ void k_input(const float* __restrict__ x, const float* __restrict__ in_w,
                        const float* __restrict__ in_b){
    int i = blockIdx.x, d = threadIdx.x;
    g_feats[0][i*DIM+d] = x[i*2+0]*in_w[d] + x[i*2+1]*in_w[DIM+d] + in_b[d];
}

// C[i][c] = sum_k A[i][k]*B[k][c] (+bias[c]); one row per block, K<=64
__global__ void k_mm(const float* __restrict__ A, int lda,
                     const float* __restrict__ B, int ldb,
                     const float* __restrict__ bias,
                     float* __restrict__ C, int ldc, int K, int Nc){
    __shared__ float sa[64];
    int i = blockIdx.x, tid = threadIdx.x;
    if (tid < K) sa[tid] = A[i*lda + tid];
    __syncthreads();
    for (int c = tid; c < Nc; c += blockDim.x){
        float s = bias ? bias[c] : 0.f;
        #pragma unroll 8
        for (int k = 0; k < K; k++) s += sa[k]*B[k*ldb + c];
        C[i*ldc + c] = s;
    }
}

__global__ void k_vp(const float* __restrict__ pb2){
    int i = blockIdx.x, d = threadIdx.x;
    g_vp[i*DIM+d] = g_qkv[i*192 + 128 + d] + pb2[d];
}

// ---------------- main per-layer pairwise kernel ----------------
// grid (NPTS/TI, JS), 256 threads. Thread (ig=tid>>6, dd=tid&63) owns the 4
// outputs (i0+ig*4+q, dd) for q=0..3 and keeps online-softmax state in regs.
__global__ __launch_bounds__(256,1) void k_layer(
        const float* __restrict__ pw2g, const float* __restrict__ aw2g,
        const float* __restrict__ ab2,  const float* __restrict__ pb1){
    extern __shared__ float sm[];
    float* s_W   = sm;             // [64][256]  16384
    float* s_aw2 = s_W   + 16384;  // [256][64]  16384
    float* s_pw2 = s_aw2 + 16384;  // [64][64]   4096
    float* s_ci  = s_pw2 + 4096;   // [16][256]  4096
    float* s_rh  = s_ci  + 4096;   // [16][256]  4096
    float* s_ai  = s_rh  + 4096;   // [16][64]   1024
    float* s_r   = s_ai  + 1024;   // [16][64]   1024
    float* s_ka  = s_r   + 1024;   // [256]
    float* s_aj  = s_ka  + 256;    // [64]
    float* s_vj  = s_aj  + 64;     // [64]

    const int tid = threadIdx.x;
    const int i0  = blockIdx.x * TI;
    const int j0  = blockIdx.y * (NPTS/JS);
    const int dd  = tid & 63;
    const int ig  = tid >> 6;          // 0..3
    const int ib  = ig * 4;            // local i base for step3

    for (int idx = tid; idx < 16384; idx += 256){ s_W[idx] = g_W[idx]; s_aw2[idx] = aw2g[idx]; }
    for (int idx = tid; idx < 4096;  idx += 256){ s_pw2[idx] = pw2g[idx]; s_ci[idx] = g_c[i0*AH + idx]; }
    for (int idx = tid; idx < 1024;  idx += 256){ s_ai[idx] = g_a[i0*DIM + idx] + pb1[idx & 63]; }
    const float ab2d = ab2[dd];

    float m0=-1e30f,m1=-1e30f,m2=-1e30f,m3=-1e30f;
    float z0=0.f,z1=0.f,z2=0.f,z3=0.f;
    float o0=0.f,o1=0.f,o2=0.f,o3=0.f;

    for (int j = j0; j < j0 + (NPTS/JS); j++){
        __syncthreads();
        if (tid < 64){ s_aj[tid] = g_a[j*DIM + tid]; s_vj[tid] = g_vp[j*DIM + tid]; }
        s_ka[tid] = g_ka[j*AH + tid];
        __syncthreads();
        #pragma unroll
        for (int q = 0; q < 4; q++){
            int idx = tid + q*256;                 // idx = i*64 + k
            s_r[idx] = fmaxf(s_ai[idx] - s_aj[idx & 63], 0.f);
        }
        __syncthreads();

        // ---- step 2: h[i][t] = c_i[t] - ka_j[t] + r_i @ W[:,t], t = tid ----
        float h[TI];
        #pragma unroll
        for (int i = 0; i < TI; i++) h[i] = s_ci[i*AH + tid] - s_ka[tid];
        #pragma unroll 4
        for (int k = 0; k < 64; k += 4){
            float w0 = s_W[(k+0)*AH + tid], w1 = s_W[(k+1)*AH + tid];
            float w2 = s_W[(k+2)*AH + tid], w3 = s_W[(k+3)*AH + tid];
            #pragma unroll
            for (int i = 0; i < TI; i++){
                float4 r4 = *(const float4*)&s_r[i*64 + k];
                h[i] += r4.x*w0 + r4.y*w1 + r4.z*w2 + r4.w*w3;
            }
        }
        #pragma unroll
        for (int i = 0; i < TI; i++) s_rh[i*AH + tid] = fmaxf(h[i], 0.f);
        __syncthreads();

        // ---- step 3: sim = rh @ aw2[:,dd] + ab2 ; e = r @ pw2[:,dd] ----
        float s0=ab2d, s1=ab2d, s2=ab2d, s3=ab2d;
        #pragma unroll 8
        for (int t = 0; t < AH; t += 4){
            float w0 = s_aw2[(t+0)*64 + dd], w1 = s_aw2[(t+1)*64 + dd];
            float w2 = s_aw2[(t+2)*64 + dd], w3 = s_aw2[(t+3)*64 + dd];
            float4 a0 = *(const float4*)&s_rh[(ib+0)*AH + t];
            float4 a1 = *(const float4*)&s_rh[(ib+1)*AH + t];
            float4 a2 = *(const float4*)&s_rh[(ib+2)*AH + t];
            float4 a3 = *(const float4*)&s_rh[(ib+3)*AH + t];
            s0 += a0.x*w0 + a0.y*w1 + a0.z*w2 + a0.w*w3;
            s1 += a1.x*w0 + a1.y*w1 + a1.z*w2 + a1.w*w3;
            s2 += a2.x*w0 + a2.y*w1 + a2.z*w2 + a2.w*w3;
            s3 += a3.x*w0 + a3.y*w1 + a3.z*w2 + a3.w*w3;
        }
        float e0=0.f,e1=0.f,e2=0.f,e3=0.f;
        #pragma unroll 4
        for (int k = 0; k < 64; k += 4){
            float w0 = s_pw2[(k+0)*64 + dd], w1 = s_pw2[(k+1)*64 + dd];
            float w2 = s_pw2[(k+2)*64 + dd], w3 = s_pw2[(k+3)*64 + dd];
            float4 a0 = *(const float4*)&s_r[(ib+0)*64 + k];
            float4 a1 = *(const float4*)&s_r[(ib+1)*64 + k];
            float4 a2 = *(const float4*)&s_r[(ib+2)*64 + k];
            float4 a3 = *(const float4*)&s_r[(ib+3)*64 + k];
            e0 += a0.x*w0 + a0.y*w1 + a0.z*w2 + a0.w*w3;
            e1 += a1.x*w0 + a1.y*w1 + a1.z*w2 + a1.w*w3;
            e2 += a2.x*w0 + a2.y*w1 + a2.z*w2 + a2.w*w3;
            e3 += a3.x*w0 + a3.y*w1 + a3.z*w2 + a3.w*w3;
        }
        const float vj = s_vj[dd];
        { float vv=vj+e0; float mn=fmaxf(m0,s0); float sc=__expf(m0-mn); float p=__expf(s0-mn);
          z0=z0*sc+p; o0=o0*sc+p*vv; m0=mn; }
        { float vv=vj+e1; float mn=fmaxf(m1,s1); float sc=__expf(m1-mn); float p=__expf(s1-mn);
          z1=z1*sc+p; o1=o1*sc+p*vv; m1=mn; }
        { float vv=vj+e2; float mn=fmaxf(m2,s2); float sc=__expf(m2-mn); float p=__expf(s2-mn);
          z2=z2*sc+p; o2=o2*sc+p*vv; m2=mn; }
        { float vv=vj+e3; float mn=fmaxf(m3,s3); float sc=__expf(m3-mn); float p=__expf(s3-mn);
          z3=z3*sc+p; o3=o3*sc+p*vv; m3=mn; }
    }

    int base = blockIdx.y*(NPTS*DIM) + (i0 + ib)*DIM + dd;
    g_pm[base+0*DIM]=m0; g_ps[base+0*DIM]=z0; g_pa[base+0*DIM]=o0;
    g_pm[base+1*DIM]=m1; g_ps[base+1*DIM]=z1; g_pa[base+1*DIM]=o1;
    g_pm[base+2*DIM]=m2; g_ps[base+2*DIM]=z2; g_pa[base+2*DIM]=o2;
    g_pm[base+3*DIM]=m3; g_ps[base+3*DIM]=z3; g_pa[base+3*DIM]=o3;
}

__global__ void k_merge(float* __restrict__ fout){
    int i = blockIdx.x, d = threadIdx.x;
    int base = i*DIM + d;
    float M = -1e30f;
    #pragma unroll
    for (int s = 0; s < JS; s++) M = fmaxf(M, g_pm[s*NPTS*DIM + base]);
    float S = 0.f, A = 0.f;
    #pragma unroll
    for (int s = 0; s < JS; s++){
        float w = __expf(g_pm[s*NPTS*DIM + base] - M);
        S += g_ps[s*NPTS*DIM + base]*w;
        A += g_pa[s*NPTS*DIM + base]*w;
    }
    fout[base] = A / S;
}

// out[i][j] = sigmoid(dot(f1_i, f1_j)); 16x16 tile per block
__global__ void k_edges(float* __restrict__ out){
    __shared__ float sfi[16][65], sfj[16][65];
    int bi = blockIdx.y*16, bj = blockIdx.x*16;
    int tid = threadIdx.x;
    for (int idx = tid; idx < 1024; idx += 256){
        int r = idx >> 6, k = idx & 63;
        sfi[r][k] = g_f1[(bi+r)*DIM + k];
        sfj[r][k] = g_f1[(bj+r)*DIM + k];
    }
    __syncthreads();
    int ti = tid >> 4, tj = tid & 15;
    float s = 0.f;
    #pragma unroll
    for (int k = 0; k < 64; k++) s += sfi[ti][k]*sfj[tj][k];
    out[(bi+ti)*NPTS + (bj+tj)] = 1.f/(1.f + __expf(-s));
}

// ---------------- host launcher ----------------
extern "C" void kernel_launch(void* const* d_in, const int* in_sizes, int n_in,
                              void* d_out, int out_size){
    const float* x     = (const float*)d_in[0];
    const float* in_w  = (const float*)d_in[1];
    const float* in_b  = (const float*)d_in[2];
    const float* qkv_w = (const float*)d_in[3];
    const float* pw1   = (const float*)d_in[4];
    const float* pb1   = (const float*)d_in[5];
    const float* pw2   = (const float*)d_in[6];
    const float* pb2   = (const float*)d_in[7];
    const float* aw1   = (const float*)d_in[8];
    const float* ab1   = (const float*)d_in[9];
    const float* aw2   = (const float*)d_in[10];
    const float* ab2   = (const float*)d_in[11];
    const float* fc_w  = (const float*)d_in[12];
    const float* fc_b  = (const float*)d_in[13];
    float* out = (float*)d_out;

    void *vp_feats, *vp_qkv, *vp_a, *vp_c, *vp_ka, *vp_W, *vp_cb, *vp_f1;
    cudaGetSymbolAddress(&vp_feats, g_feats);
    cudaGetSymbolAddress(&vp_qkv,   g_qkv);
    cudaGetSymbolAddress(&vp_a,     g_a);
    cudaGetSymbolAddress(&vp_c,     g_c);
    cudaGetSymbolAddress(&vp_ka,    g_ka);
    cudaGetSymbolAddress(&vp_W,     g_W);
    cudaGetSymbolAddress(&vp_cb,    g_cbias);
    cudaGetSymbolAddress(&vp_f1,    g_f1);
    float* p_feats = (float*)vp_feats;   // [2][NPTS*DIM]
    float* p_qkv   = (float*)vp_qkv;
    float* p_a     = (float*)vp_a;
    float* p_c     = (float*)vp_c;
    float* p_ka    = (float*)vp_ka;
    float* p_W     = (float*)vp_W;
    float* p_cb    = (float*)vp_cb;
    float* p_f1    = (float*)vp_f1;

    const size_t SMEM = 47488u * sizeof(float);   // 189,952 B
    cudaFuncSetAttribute(k_layer, cudaFuncAttributeMaxDynamicSharedMemorySize, (int)SMEM);

    k_input<<<NPTS, DIM>>>(x, in_w, in_b);

    int cur = 0;
    for (int l = 0; l < 3; l++){
        const float* aw1l = aw1 + (size_t)l*64*256;
        // qkv = feats @ qkv_w[l]
        k_mm<<<NPTS,256>>>(p_feats + cur*NPTS*DIM, 64, qkv_w + (size_t)l*64*192, 192,
                           nullptr, p_qkv, 192, 64, 192);
        // a = pos @ pw1[l]  (pos z==0 -> only first 2 rows of pw1)
        k_mm<<<NPTS,256>>>(x, 2, pw1 + (size_t)l*3*64, 64, nullptr, p_a, 64, 2, 64);
        // W = pw2[l] @ aw1[l]
        k_mm<<<64,256>>>(pw2 + (size_t)l*64*64, 64, aw1l, 256, nullptr, p_W, 256, 64, 256);
        // cbias = pb2[l] @ aw1[l] + ab1[l]
        k_mm<<<1,256>>>(pb2 + (size_t)l*64, 64, aw1l, 256, ab1 + (size_t)l*256, p_cb, 256, 64, 256);
        // ka = k @ aw1[l]
        k_mm<<<NPTS,256>>>(p_qkv + 64, 192, aw1l, 256, nullptr, p_ka, 256, 64, 256);
        // c = q @ aw1[l] + cbias
        k_mm<<<NPTS,256>>>(p_qkv, 192, aw1l, 256, p_cb, p_c, 256, 64, 256);
        // vp = v + pb2[l]
        k_vp<<<NPTS,DIM>>>(pb2 + (size_t)l*64);

        dim3 g(NPTS/TI, JS);
        k_layer<<<g, 256, SMEM>>>(pw2 + (size_t)l*64*64, aw2 + (size_t)l*256*64,
                                  ab2 + (size_t)l*64, pb1 + (size_t)l*64);
        k_merge<<<NPTS, DIM>>>(p_feats + (1-cur)*NPTS*DIM);
        cur = 1 - cur;
    }

    // f1 = feats @ fc_w + fc_b ; out = sigmoid(f1 @ f1^T)
    k_mm<<<NPTS,256>>>(p_feats + cur*NPTS*DIM, 64, fc_w, 64, fc_b, p_f1, 64, 64, 64);
    dim3 ge(NPTS/16, NPTS/16);
    k_edges<<<ge, 256>>>(out);
}